// round 1
// baseline (speedup 1.0000x reference)
#include <cuda_runtime.h>

#define BB 512
#define TT 168
#define HH 512
#define GG 2048   // 4*H
#define GI 8      // batch slices
#define GJ 16     // unit slices
#define NCTA (GI*GJ)   // 128 persistent CTAs (<= 148 SMs, all resident)
#define RB 64     // batch rows per CTA
#define UN 32     // hidden units per CTA (x4 gates = 128 gate cols)
#define GC 128
#define KC 32     // K chunk
#define NTHR 256

// ---- static device scratch (no allocations allowed) ----
__device__ float g_h1[2][BB][HH];          // 2 MB double-buffered layer-1 hidden
__device__ float g_h2[2][BB][HH];          // 2 MB double-buffered layer-2 hidden
__device__ float g_partial[GJ][BB * TT];   // per-unit-slice partial fc dots
__device__ unsigned g_bar_cnt;             // returns to 0 every barrier -> replay-safe
__device__ volatile unsigned g_bar_gen;    // monotonically increasing generation

__device__ __forceinline__ float sigmoidf_(float x) {
    return 1.0f / (1.0f + __expf(-x));
}

// Sense-free generation barrier. All 128 CTAs are guaranteed co-resident
// (1 CTA/SM, 256 threads, <48KB static smem), so spinning is deadlock-free.
__device__ __forceinline__ void grid_sync_() {
    __syncthreads();
    if (threadIdx.x == 0) {
        __threadfence();                       // publish h writes
        unsigned gen = g_bar_gen;
        if (atomicAdd(&g_bar_cnt, 1u) == NCTA - 1u) {
            g_bar_cnt = 0u;
            __threadfence();
            g_bar_gen = gen + 1u;
        } else {
            while (g_bar_gen == gen) { }
            __threadfence();                   // acquire
        }
    }
    __syncthreads();
}

struct Smem {
    float As[RB][33];        // A tile, padded: conflict-free stores & broadcast reads
    float Ws[KC][GC];        // W tile, [k][q*32+u]
    float W1c[GC], b1c[GC], b2c[GC];
    float V1c[4][GC], V2c[4][GC];
    float fcwc[UN];
    float red[UN][RB + 1];   // padded 65-stride: conflict-free reduce
};

// acc[8 rows][4 gates] += A[64 x 512] * Wslice[512 x 128]
// A: row stride HH. W: row stride GG; local col (q,u) -> global col q*HH + ubase + u.
__device__ __forceinline__ void gemm_acc(const float* __restrict__ A,
                                         const float* __restrict__ W,
                                         int ubase, float acc[8][4],
                                         Smem* s, int rg, int u) {
    const int tid = threadIdx.x;
    const int rA = tid >> 2;            // 0..63
    const int kl = (tid & 3) << 3;      // 0,8,16,24
    const int cc = tid & 127;
    const int kb = tid >> 7;            // 0 or 1
    const int q  = cc >> 5;
    const int uu = cc & 31;

    for (int k0 = 0; k0 < HH; k0 += KC) {
        __syncthreads();
        // --- load A tile (coalesced float4 x2 per thread) ---
        {
            const float4* src = reinterpret_cast<const float4*>(A + (size_t)rA * HH + k0 + kl);
            float4 v0 = src[0], v1 = src[1];
            float* dst = &s->As[rA][kl];
            dst[0] = v0.x; dst[1] = v0.y; dst[2] = v0.z; dst[3] = v0.w;
            dst[4] = v1.x; dst[5] = v1.y; dst[6] = v1.z; dst[7] = v1.w;
        }
        // --- load W tile: 32k x 128c, 128B-coalesced runs ---
        {
            const float* wp = W + (size_t)(k0 + kb) * GG + q * HH + ubase + uu;
            #pragma unroll
            for (int kk = 0; kk < KC; kk += 2)
                s->Ws[kk + kb][cc] = wp[(size_t)kk * GG];
        }
        __syncthreads();
        // --- micro-kernel: 8x4 per thread ---
        #pragma unroll 4
        for (int k = 0; k < KC; k++) {
            float a[8], w[4];
            #pragma unroll
            for (int rr = 0; rr < 8; rr++) a[rr] = s->As[rg * 8 + rr][k];
            #pragma unroll
            for (int qq = 0; qq < 4; qq++) w[qq] = s->Ws[k][qq * 32 + u];
            #pragma unroll
            for (int rr = 0; rr < 8; rr++)
                #pragma unroll
                for (int qq = 0; qq < 4; qq++)
                    acc[rr][qq] = fmaf(a[rr], w[qq], acc[rr][qq]);
        }
    }
}

__global__ void __launch_bounds__(NTHR, 1)
pew_kernel(const float* __restrict__ inputs, const float* __restrict__ W1,
           const float* __restrict__ U1, const float* __restrict__ V1,
           const float* __restrict__ b1, const float* __restrict__ W2,
           const float* __restrict__ U2, const float* __restrict__ V2,
           const float* __restrict__ b2, const float* __restrict__ fc_w) {
    __shared__ Smem s;
    const int tid = threadIdx.x;
    const int bi = blockIdx.x >> 4;   // / GJ
    const int bj = blockIdx.x & 15;   // % GJ
    const int bbase = bi * RB;
    const int ubase = bj * UN;
    const int u  = tid & 31;
    const int rg = tid >> 5;

    // cache per-CTA gate-column constants
    for (int c = tid; c < GC; c += NTHR) {
        int q = c >> 5, uu = c & 31;
        int gcol = q * HH + ubase + uu;
        s.W1c[c] = W1[gcol];
        s.b1c[c] = b1[gcol];
        s.b2c[c] = b2[gcol];
        #pragma unroll
        for (int w = 0; w < 4; w++) {
            s.V1c[w][c] = V1[w * GG + gcol];
            s.V2c[w][c] = V2[w * GG + gcol];
        }
    }
    if (tid < UN) s.fcwc[tid] = fc_w[ubase + tid];
    __syncthreads();

    float c1[8], c2[8];
    #pragma unroll
    for (int rr = 0; rr < 8; rr++) { c1[rr] = 0.f; c2[rr] = 0.f; }

    for (int t = 0; t < TT; t++) {
        const int cur = t & 1, prev = cur ^ 1;

        // ================= layer 1 =================
        float acc[8][4];
        #pragma unroll
        for (int rr = 0; rr < 8; rr++)
            #pragma unroll
            for (int q = 0; q < 4; q++) acc[rr][q] = 0.f;

        if (t > 0) gemm_acc(&g_h1[prev][bbase][0], U1, ubase, acc, &s, rg, u);

        #pragma unroll
        for (int rr = 0; rr < 8; rr++) {
            int b_ = bbase + rg * 8 + rr;
            const float* inp = inputs + ((size_t)b_ * TT + t) * 5;
            float w0 = inp[0], w1 = inp[1], w2 = inp[2], w3 = inp[3], x = inp[4];
            #pragma unroll
            for (int q = 0; q < 4; q++) {
                int c = q * 32 + u;
                float p = s.b1c[c];
                p = fmaf(x,  s.W1c[c],    p);
                p = fmaf(w0, s.V1c[0][c], p);
                p = fmaf(w1, s.V1c[1][c], p);
                p = fmaf(w2, s.V1c[2][c], p);
                p = fmaf(w3, s.V1c[3][c], p);
                acc[rr][q] += p;
            }
            float ig = sigmoidf_(acc[rr][0]);
            float fg = sigmoidf_(acc[rr][1]);
            float gv = tanhf(acc[rr][2]);
            float og = sigmoidf_(acc[rr][3]);
            c1[rr] = fmaf(fg, c1[rr], ig * gv);
            g_h1[cur][b_][ubase + u] = og * tanhf(c1[rr]);
        }

        grid_sync_();   // publish h1_t; also covers h2_{t-1} from previous iter

        // ================= layer 2 =================
        #pragma unroll
        for (int rr = 0; rr < 8; rr++)
            #pragma unroll
            for (int q = 0; q < 4; q++) acc[rr][q] = 0.f;

        gemm_acc(&g_h1[cur][bbase][0], W2, ubase, acc, &s, rg, u);
        if (t > 0) gemm_acc(&g_h2[prev][bbase][0], U2, ubase, acc, &s, rg, u);

        #pragma unroll
        for (int rr = 0; rr < 8; rr++) {
            int b_ = bbase + rg * 8 + rr;
            const float* inp = inputs + ((size_t)b_ * TT + t) * 5;
            float w0 = inp[0], w1 = inp[1], w2 = inp[2], w3 = inp[3];
            #pragma unroll
            for (int q = 0; q < 4; q++) {
                int c = q * 32 + u;
                float p = s.b2c[c];
                p = fmaf(w0, s.V2c[0][c], p);
                p = fmaf(w1, s.V2c[1][c], p);
                p = fmaf(w2, s.V2c[2][c], p);
                p = fmaf(w3, s.V2c[3][c], p);
                acc[rr][q] += p;
            }
            float ig = sigmoidf_(acc[rr][0]);
            float fg = sigmoidf_(acc[rr][1]);
            float gv = tanhf(acc[rr][2]);
            float og = sigmoidf_(acc[rr][3]);
            c2[rr] = fmaf(fg, c2[rr], ig * gv);
            float hv = og * tanhf(c2[rr]);
            g_h2[cur][b_][ubase + u] = hv;
            s.red[u][rg * 8 + rr] = hv * s.fcwc[u];
        }
        __syncthreads();
        if (tid < RB) {
            float sum = 0.f;
            #pragma unroll
            for (int uu2 = 0; uu2 < UN; uu2++) sum += s.red[uu2][tid];
            g_partial[bj][(size_t)(bbase + tid) * TT + t] = sum;
        }
        // next gemm_acc starts with __syncthreads(), protecting s reuse
    }
}

__global__ void reduce_kernel(float* __restrict__ out, const float* __restrict__ fc_b) {
    int n = blockIdx.x * blockDim.x + threadIdx.x;
    if (n < BB * TT) {
        float sv = fc_b[0];
        #pragma unroll
        for (int j = 0; j < GJ; j++) sv += g_partial[j][n];
        out[n] = sv;
    }
}

extern "C" void kernel_launch(void* const* d_in, const int* in_sizes, int n_in,
                              void* d_out, int out_size) {
    const float* inputs = (const float*)d_in[0];
    const float* W1  = (const float*)d_in[1];
    const float* U1  = (const float*)d_in[2];
    const float* V1  = (const float*)d_in[3];
    const float* b1  = (const float*)d_in[4];
    const float* W2  = (const float*)d_in[5];
    const float* U2  = (const float*)d_in[6];
    const float* V2  = (const float*)d_in[7];
    const float* b2  = (const float*)d_in[8];
    const float* fcw = (const float*)d_in[9];
    const float* fcb = (const float*)d_in[10];

    pew_kernel<<<NCTA, NTHR>>>(inputs, W1, U1, V1, b1, W2, U2, V2, b2, fcw);
    reduce_kernel<<<(BB * TT + 255) / 256, 256>>>((float*)d_out, fcb);
}